// round 2
// baseline (speedup 1.0000x reference)
#include <cuda_runtime.h>
#include <math.h>

#define NTOK   196
#define CDIM   768
#define BATCH  256
#define NCLS   701

// Scratch: 4 mean vectors per sample, row = (tensor*2 + isFg)*BATCH + b
__device__ float g_V[4 * BATCH * CDIM];

// packed dual-fp32 FMA: d(lo,hi) += a(lo,hi)*b(lo,hi)
__device__ __forceinline__ void fma2(unsigned long long& d,
                                     unsigned long long a,
                                     unsigned long long b) {
    asm volatile("fma.rn.f32x2 %0, %1, %2, %0;" : "+l"(d) : "l"(a), "l"(b));
}
__device__ __forceinline__ float f2lo(unsigned long long v) {
    return __uint_as_float((unsigned int)v);
}
__device__ __forceinline__ float f2hi(unsigned long long v) {
    return __uint_as_float((unsigned int)(v >> 32));
}

// ---------------------------------------------------------------------------
// Kernel 1: fused SGM per (tensor, sample).
// ---------------------------------------------------------------------------
__global__ void __launch_bounds__(256)
sgm_kernel(const float* __restrict__ x1, const float* __restrict__ x2) {
    const int b      = blockIdx.x;
    const int tensor = blockIdx.y;
    const float* x = (tensor == 0 ? x1 : x2) + (size_t)b * NTOK * CDIM;

    __shared__ float sT[8][CDIM];     // per-warp channel-sum staging
    __shared__ float sTtot[CDIM];     // final per-channel totals
    __shared__ float sM[NTOK];        // token energies
    __shared__ float sSorted[NTOK];   // sorted normalized energies
    __shared__ float sVal[256];       // generic reduce buffer (also holds Mn)
    __shared__ int   sIdx[256];
    __shared__ int   sList[112];      // small-side token indices
    __shared__ int   sCnt;
    __shared__ float sMnMx[2];

    const int tid  = threadIdx.x;
    const int warp = tid >> 5;
    const int lane = tid & 31;

    // ---------------- Pass 1: M[n] and T[c], 2 rows/iter for MLP ----------------
    float tacc[24];
#pragma unroll
    for (int i = 0; i < 24; i++) tacc[i] = 0.f;

    int n = warp;
    for (; n + 8 < NTOK; n += 16) {
        const float4* rowA = reinterpret_cast<const float4*>(x + (size_t)n * CDIM);
        const float4* rowB = reinterpret_cast<const float4*>(x + (size_t)(n + 8) * CDIM);
        float msA = 0.f, msB = 0.f;
#pragma unroll
        for (int i = 0; i < 6; i++) {
            float4 va = rowA[lane + 32 * i];
            float4 vb = rowB[lane + 32 * i];
            tacc[4*i+0] += va.x + vb.x; tacc[4*i+1] += va.y + vb.y;
            tacc[4*i+2] += va.z + vb.z; tacc[4*i+3] += va.w + vb.w;
            msA += (va.x + va.y) + (va.z + va.w);
            msB += (vb.x + vb.y) + (vb.z + vb.w);
        }
#pragma unroll
        for (int off = 16; off > 0; off >>= 1) {
            msA += __shfl_down_sync(0xffffffffu, msA, off);
            msB += __shfl_down_sync(0xffffffffu, msB, off);
        }
        if (lane == 0) { sM[n] = msA; sM[n + 8] = msB; }
    }
    if (n < NTOK) {
        const float4* row = reinterpret_cast<const float4*>(x + (size_t)n * CDIM);
        float msum = 0.f;
#pragma unroll
        for (int i = 0; i < 6; i++) {
            float4 v = row[lane + 32 * i];
            tacc[4*i+0] += v.x; tacc[4*i+1] += v.y;
            tacc[4*i+2] += v.z; tacc[4*i+3] += v.w;
            msum += (v.x + v.y) + (v.z + v.w);
        }
#pragma unroll
        for (int off = 16; off > 0; off >>= 1)
            msum += __shfl_down_sync(0xffffffffu, msum, off);
        if (lane == 0) sM[n] = msum;
    }
    {
        float4* st = reinterpret_cast<float4*>(&sT[warp][0]);
#pragma unroll
        for (int i = 0; i < 6; i++)
            st[lane + 32 * i] = make_float4(tacc[4*i], tacc[4*i+1], tacc[4*i+2], tacc[4*i+3]);
    }
    if (tid == 0) sCnt = 0;
    __syncthreads();

    if (tid < 192) {  // 192 float4 = 768 channels
        float4 t = make_float4(0.f, 0.f, 0.f, 0.f);
#pragma unroll
        for (int w = 0; w < 8; w++) {
            float4 v = reinterpret_cast<float4*>(&sT[w][0])[tid];
            t.x += v.x; t.y += v.y; t.z += v.z; t.w += v.w;
        }
        reinterpret_cast<float4*>(sTtot)[tid] = t;
    }
    __syncthreads();

    // ---------------- min / max of M ----------------
    sVal[tid] = (tid < NTOK) ? sM[tid] : 3.4e38f;
    __syncthreads();
    for (int s = 128; s > 0; s >>= 1) {
        if (tid < s) sVal[tid] = fminf(sVal[tid], sVal[tid + s]);
        __syncthreads();
    }
    if (tid == 0) sMnMx[0] = sVal[0];
    __syncthreads();
    sVal[tid] = (tid < NTOK) ? sM[tid] : -3.4e38f;
    __syncthreads();
    for (int s = 128; s > 0; s >>= 1) {
        if (tid < s) sVal[tid] = fmaxf(sVal[tid], sVal[tid + s]);
        __syncthreads();
    }
    if (tid == 0) sMnMx[1] = sVal[0];
    __syncthreads();

    const float mn  = sMnMx[0];
    const float mx  = sMnMx[1];
    const float inv = 1.f / (mx - mn);

    // ---------------- normalize + stable rank ----------------
    float myMn = 0.f;
    __syncthreads();
    if (tid < NTOK) myMn = (sM[tid] - mn) * inv;
    sVal[tid] = myMn;
    __syncthreads();

    int myrank = 0;
    if (tid < NTOK) {
        int r = 0;
        for (int m = 0; m < NTOK; m++) {
            float o = sVal[m];
            r += (o < myMn) || (o == myMn && m < tid);   // stable (argsort) order
        }
        myrank = r;
        sSorted[r] = myMn;
    }
    __syncthreads();

    // ---------------- gap diff + argmax (first index on ties) ----------------
    float dv = -1.f;
    if (tid < NTOK - 1) {
        float s0 = sSorted[tid];
        dv = (s0 == 0.f) ? 0.f : (sSorted[tid + 1] - s0);
    }
    sVal[tid] = dv;
    sIdx[tid] = tid;
    __syncthreads();
    for (int s = 128; s > 0; s >>= 1) {
        if (tid < s) {
            float v2 = sVal[tid + s]; int i2 = sIdx[tid + s];
            if (v2 > sVal[tid] || (v2 == sVal[tid] && i2 < sIdx[tid])) {
                sVal[tid] = v2; sIdx[tid] = i2;
            }
        }
        __syncthreads();
    }
    const int  k         = sIdx[0];
    const bool smallIsFg = (k <= NTOK / 2);

    if (tid < NTOK) {
        bool inSmall = smallIsFg ? (myrank < k) : (myrank >= k);
        if (inSmall) {
            int p = atomicAdd(&sCnt, 1);
            sList[p] = tid;
        }
    }
    __syncthreads();
    const int cnt = sCnt;

    // ---------------- Pass 2: small-side channel sum (L2 hits) ----------------
#pragma unroll
    for (int i = 0; i < 24; i++) tacc[i] = 0.f;
    for (int j = warp; j < cnt; j += 8) {
        int nn = sList[j];
        const float4* row = reinterpret_cast<const float4*>(x + (size_t)nn * CDIM);
#pragma unroll
        for (int i = 0; i < 6; i++) {
            float4 v = row[lane + 32 * i];
            tacc[4*i+0] += v.x; tacc[4*i+1] += v.y;
            tacc[4*i+2] += v.z; tacc[4*i+3] += v.w;
        }
    }
    {
        float4* st = reinterpret_cast<float4*>(&sT[warp][0]);
#pragma unroll
        for (int i = 0; i < 6; i++)
            st[lane + 32 * i] = make_float4(tacc[4*i], tacc[4*i+1], tacc[4*i+2], tacc[4*i+3]);
    }
    __syncthreads();

    if (tid < 192) {
        float4 S = make_float4(0.f, 0.f, 0.f, 0.f);
#pragma unroll
        for (int w = 0; w < 8; w++) {
            float4 v = reinterpret_cast<float4*>(&sT[w][0])[tid];
            S.x += v.x; S.y += v.y; S.z += v.z; S.w += v.w;
        }
        float4 T = reinterpret_cast<float4*>(sTtot)[tid];

        float4 fgs, bgs;
        if (smallIsFg) {
            fgs = S;
            bgs = make_float4(T.x - S.x, T.y - S.y, T.z - S.z, T.w - S.w);
        } else {
            bgs = S;
            fgs = make_float4(T.x - S.x, T.y - S.y, T.z - S.z, T.w - S.w);
        }
        const float fgc = fmaxf((float)k, 1.f);
        const float bgc = fmaxf((float)(NTOK - k), 1.f);
        float4 fg = make_float4(fgs.x / fgc, fgs.y / fgc, fgs.z / fgc, fgs.w / fgc);
        float4 bg = make_float4(bgs.x / bgc, bgs.y / bgc, bgs.z / bgc, bgs.w / bgc);

        float4* vbg = reinterpret_cast<float4*>(&g_V[(size_t)((tensor * 2 + 0) * BATCH + b) * CDIM]);
        float4* vfg = reinterpret_cast<float4*>(&g_V[(size_t)((tensor * 2 + 1) * BATCH + b) * CDIM]);
        vbg[tid] = bg;
        vfg[tid] = fg;
    }
}

// ---------------------------------------------------------------------------
// Kernel 2: out[1024,701] = g_V[1024,768] @ W[768,701] + bias
// 32x32 tiles, 64 threads, 4x4 microtile via packed fma.rn.f32x2.
// A+W are L2-resident (5.3 MB) -> pure FMA-throughput problem; small tiles
// give 704 blocks -> near-perfect chip balance.
// ---------------------------------------------------------------------------
#define BM 32
#define BN 32
#define BK 16

__global__ void __launch_bounds__(64)
gemm_kernel(const float* __restrict__ W, const float* __restrict__ bias,
            float* __restrict__ out) {
    __shared__ __align__(16) float  As[BK][36];      // [k][m], pad 4 (16B-mult rows)
    __shared__ __align__(16) float2 Bsr[BK][BN];     // replicated (w,w) pairs

    const int tid = threadIdx.x;
    const int ty  = tid >> 3;           // 0..7 -> 4 m-rows (2 packed pairs)
    const int tx  = tid & 7;            // 0..7 -> 4 n-cols
    const int r0  = blockIdx.y * BM;
    const int c0  = blockIdx.x * BN;

    unsigned long long acc[2][4];
#pragma unroll
    for (int p = 0; p < 2; p++)
#pragma unroll
        for (int q = 0; q < 4; q++) acc[p][q] = 0ULL;

    for (int k0 = 0; k0 < CDIM; k0 += BK) {
        // A tile: 32 rows x 16 k = 128 float4, 2 per thread, store transposed
#pragma unroll
        for (int i = 0; i < 2; i++) {
            int f  = tid + 64 * i;
            int m  = f >> 2;
            int c4 = f & 3;
            float4 va = *reinterpret_cast<const float4*>(
                &g_V[(size_t)(r0 + m) * CDIM + k0 + 4 * c4]);
            As[4*c4+0][m] = va.x;
            As[4*c4+1][m] = va.y;
            As[4*c4+2][m] = va.z;
            As[4*c4+3][m] = va.w;
        }
        // B tile: 16 k x 32 n scalars, replicated into float2
#pragma unroll
        for (int i = 0; i < 8; i++) {
            int flat = tid + 64 * i;
            int kk = flat >> 5;
            int cc = flat & 31;
            int c  = c0 + cc;
            float w = (c < NCLS) ? __ldg(&W[(size_t)(k0 + kk) * NCLS + c]) : 0.f;
            Bsr[kk][cc] = make_float2(w, w);
        }
        __syncthreads();

#pragma unroll
        for (int kk = 0; kk < BK; kk++) {
            ulonglong2 a  = *reinterpret_cast<const ulonglong2*>(&As[kk][ty * 4]);
            ulonglong2 b0 = *reinterpret_cast<const ulonglong2*>(&Bsr[kk][tx * 4]);
            ulonglong2 b1 = *reinterpret_cast<const ulonglong2*>(&Bsr[kk][tx * 4 + 2]);
            fma2(acc[0][0], a.x, b0.x); fma2(acc[0][1], a.x, b0.y);
            fma2(acc[0][2], a.x, b1.x); fma2(acc[0][3], a.x, b1.y);
            fma2(acc[1][0], a.y, b0.x); fma2(acc[1][1], a.y, b0.y);
            fma2(acc[1][2], a.y, b1.x); fma2(acc[1][3], a.y, b1.y);
        }
        __syncthreads();
    }

    const int m0 = r0 + ty * 4;
#pragma unroll
    for (int nn = 0; nn < 4; nn++) {
        int c = c0 + tx * 4 + nn;
        if (c < NCLS) {
            float bb = bias[c];
            out[(size_t)(m0 + 0) * NCLS + c] = f2lo(acc[0][nn]) + bb;
            out[(size_t)(m0 + 1) * NCLS + c] = f2hi(acc[0][nn]) + bb;
            out[(size_t)(m0 + 2) * NCLS + c] = f2lo(acc[1][nn]) + bb;
            out[(size_t)(m0 + 3) * NCLS + c] = f2hi(acc[1][nn]) + bb;
        }
    }
}

// ---------------------------------------------------------------------------
extern "C" void kernel_launch(void* const* d_in, const int* in_sizes, int n_in,
                              void* d_out, int out_size) {
    const float* x1 = nullptr;
    const float* x2 = nullptr;
    const float* W  = nullptr;
    const float* bb = nullptr;
    for (int i = 0; i < n_in; i++) {
        if (in_sizes[i] == BATCH * NTOK * CDIM) {
            if (!x1) x1 = (const float*)d_in[i];
            else if (!x2) x2 = (const float*)d_in[i];
        } else if (in_sizes[i] == CDIM * NCLS) {
            W = (const float*)d_in[i];
        } else if (in_sizes[i] == NCLS) {
            bb = (const float*)d_in[i];
        }
    }
    float* out = (float*)d_out;

    dim3 g1(BATCH, 2);
    sgm_kernel<<<g1, 256>>>(x1, x2);

    dim3 g2((NCLS + BN - 1) / BN, (4 * BATCH) / BM);
    gemm_kernel<<<g2, 64>>>(W, bb, out);
}

// round 5
// speedup vs baseline: 1.2204x; 1.2204x over previous
#include <cuda_runtime.h>
#include <cuda_bf16.h>
#include <math.h>
#include <stdint.h>

#define NTOK   196
#define CDIM   768
#define BATCH  256
#define NCLS   701

// Scratch: 4 mean vectors per sample, row = (tensor*2 + isFg)*BATCH + b
__device__ float g_V[4 * BATCH * CDIM];

__device__ __forceinline__ uint32_t smem_u32(const void* p) {
    uint32_t a;
    asm("{ .reg .u64 t; cvta.to.shared.u64 t, %1; cvt.u32.u64 %0, t; }"
        : "=r"(a) : "l"(p));
    return a;
}

// ============================================================================
// Kernel 1: fused SGM per (tensor, sample).  (R0 version — proven ~63us)
// ============================================================================
__global__ void __launch_bounds__(256)
sgm_kernel(const float* __restrict__ x1, const float* __restrict__ x2) {
    const int b      = blockIdx.x;
    const int tensor = blockIdx.y;
    const float* x = (tensor == 0 ? x1 : x2) + (size_t)b * NTOK * CDIM;

    __shared__ float sT[8][CDIM];
    __shared__ float sTtot[CDIM];
    __shared__ float sM[NTOK];
    __shared__ float sSorted[NTOK];
    __shared__ float sVal[256];
    __shared__ int   sIdx[256];
    __shared__ int   sList[112];
    __shared__ int   sCnt;
    __shared__ float sMnMx[2];

    const int tid  = threadIdx.x;
    const int warp = tid >> 5;
    const int lane = tid & 31;

    float tacc[24];
#pragma unroll
    for (int i = 0; i < 24; i++) tacc[i] = 0.f;

    for (int n = warp; n < NTOK; n += 8) {
        const float4* row = reinterpret_cast<const float4*>(x + (size_t)n * CDIM);
        float msum = 0.f;
#pragma unroll
        for (int i = 0; i < 6; i++) {
            float4 v = row[lane + 32 * i];
            tacc[4*i+0] += v.x; tacc[4*i+1] += v.y;
            tacc[4*i+2] += v.z; tacc[4*i+3] += v.w;
            msum += (v.x + v.y) + (v.z + v.w);
        }
#pragma unroll
        for (int off = 16; off > 0; off >>= 1)
            msum += __shfl_down_sync(0xffffffffu, msum, off);
        if (lane == 0) sM[n] = msum;
    }
    {
        float4* st = reinterpret_cast<float4*>(&sT[warp][0]);
#pragma unroll
        for (int i = 0; i < 6; i++)
            st[lane + 32 * i] = make_float4(tacc[4*i], tacc[4*i+1], tacc[4*i+2], tacc[4*i+3]);
    }
    if (tid == 0) sCnt = 0;
    __syncthreads();

    if (tid < 192) {
        float4 t = make_float4(0.f, 0.f, 0.f, 0.f);
#pragma unroll
        for (int w = 0; w < 8; w++) {
            float4 v = reinterpret_cast<float4*>(&sT[w][0])[tid];
            t.x += v.x; t.y += v.y; t.z += v.z; t.w += v.w;
        }
        reinterpret_cast<float4*>(sTtot)[tid] = t;
    }
    __syncthreads();

    sVal[tid] = (tid < NTOK) ? sM[tid] : 3.4e38f;
    __syncthreads();
    for (int s = 128; s > 0; s >>= 1) {
        if (tid < s) sVal[tid] = fminf(sVal[tid], sVal[tid + s]);
        __syncthreads();
    }
    if (tid == 0) sMnMx[0] = sVal[0];
    __syncthreads();
    sVal[tid] = (tid < NTOK) ? sM[tid] : -3.4e38f;
    __syncthreads();
    for (int s = 128; s > 0; s >>= 1) {
        if (tid < s) sVal[tid] = fmaxf(sVal[tid], sVal[tid + s]);
        __syncthreads();
    }
    if (tid == 0) sMnMx[1] = sVal[0];
    __syncthreads();

    const float mn  = sMnMx[0];
    const float mx  = sMnMx[1];
    const float inv = 1.f / (mx - mn);

    float myMn = 0.f;
    __syncthreads();
    if (tid < NTOK) myMn = (sM[tid] - mn) * inv;
    sVal[tid] = myMn;
    __syncthreads();

    int myrank = 0;
    if (tid < NTOK) {
        int r = 0;
        for (int m = 0; m < NTOK; m++) {
            float o = sVal[m];
            r += (o < myMn) || (o == myMn && m < tid);
        }
        myrank = r;
        sSorted[r] = myMn;
    }
    __syncthreads();

    float dv = -1.f;
    if (tid < NTOK - 1) {
        float s0 = sSorted[tid];
        dv = (s0 == 0.f) ? 0.f : (sSorted[tid + 1] - s0);
    }
    sVal[tid] = dv;
    sIdx[tid] = tid;
    __syncthreads();
    for (int s = 128; s > 0; s >>= 1) {
        if (tid < s) {
            float v2 = sVal[tid + s]; int i2 = sIdx[tid + s];
            if (v2 > sVal[tid] || (v2 == sVal[tid] && i2 < sIdx[tid])) {
                sVal[tid] = v2; sIdx[tid] = i2;
            }
        }
        __syncthreads();
    }
    const int  k         = sIdx[0];
    const bool smallIsFg = (k <= NTOK / 2);

    if (tid < NTOK) {
        bool inSmall = smallIsFg ? (myrank < k) : (myrank >= k);
        if (inSmall) {
            int p = atomicAdd(&sCnt, 1);
            sList[p] = tid;
        }
    }
    __syncthreads();
    const int cnt = sCnt;

#pragma unroll
    for (int i = 0; i < 24; i++) tacc[i] = 0.f;
    for (int j = warp; j < cnt; j += 8) {
        int nn = sList[j];
        const float4* row = reinterpret_cast<const float4*>(x + (size_t)nn * CDIM);
#pragma unroll
        for (int i = 0; i < 6; i++) {
            float4 v = row[lane + 32 * i];
            tacc[4*i+0] += v.x; tacc[4*i+1] += v.y;
            tacc[4*i+2] += v.z; tacc[4*i+3] += v.w;
        }
    }
    {
        float4* st = reinterpret_cast<float4*>(&sT[warp][0]);
#pragma unroll
        for (int i = 0; i < 6; i++)
            st[lane + 32 * i] = make_float4(tacc[4*i], tacc[4*i+1], tacc[4*i+2], tacc[4*i+3]);
    }
    __syncthreads();

    if (tid < 192) {
        float4 S = make_float4(0.f, 0.f, 0.f, 0.f);
#pragma unroll
        for (int w = 0; w < 8; w++) {
            float4 v = reinterpret_cast<float4*>(&sT[w][0])[tid];
            S.x += v.x; S.y += v.y; S.z += v.z; S.w += v.w;
        }
        float4 T = reinterpret_cast<float4*>(sTtot)[tid];

        float4 fgs, bgs;
        if (smallIsFg) {
            fgs = S;
            bgs = make_float4(T.x - S.x, T.y - S.y, T.z - S.z, T.w - S.w);
        } else {
            bgs = S;
            fgs = make_float4(T.x - S.x, T.y - S.y, T.z - S.z, T.w - S.w);
        }
        const float fgc = fmaxf((float)k, 1.f);
        const float bgc = fmaxf((float)(NTOK - k), 1.f);
        float4 fg = make_float4(fgs.x / fgc, fgs.y / fgc, fgs.z / fgc, fgs.w / fgc);
        float4 bg = make_float4(bgs.x / bgc, bgs.y / bgc, bgs.z / bgc, bgs.w / bgc);

        float4* vbg = reinterpret_cast<float4*>(&g_V[(size_t)((tensor * 2 + 0) * BATCH + b) * CDIM]);
        float4* vfg = reinterpret_cast<float4*>(&g_V[(size_t)((tensor * 2 + 1) * BATCH + b) * CDIM]);
        vbg[tid] = bg;
        vfg[tid] = fg;
    }
}

// ============================================================================
// Kernel 2: HMMA (mma.sync m16n8k16 bf16->f32) GEMM with bf16 hi/lo split.
//   out[1024,701] = g_V[1024,768] @ W[768,701] + bias
//   A = Ah+Al, B = Bh+Bl (bf16); acc += AhBh + AhBl + AlBh  (fp32 accum)
// Block: BM=32 x BN=64, 128 threads (2x2 warps, warp tile 16x32), BK=64.
// Grid: 32 x 11 = 352 blocks.
// NOTE: W rows have stride 701 floats (odd) -> W must be loaded SCALAR.
// ============================================================================
#define GBM 32
#define GBN 64
#define GBK 64
#define PA  72          // bf16 pitch for A rows (64+8): 144B -> 16B-aligned rows
#define PB  72          // bf16 pitch for B rows (64+8)
#define NSTAGE (CDIM / GBK)   // 12

__device__ __forceinline__ void ldm_x4(uint32_t r[4], uint32_t addr) {
    asm volatile("ldmatrix.sync.aligned.m8n8.x4.shared.b16 {%0,%1,%2,%3}, [%4];"
                 : "=r"(r[0]), "=r"(r[1]), "=r"(r[2]), "=r"(r[3]) : "r"(addr));
}
__device__ __forceinline__ void ldm_x4_t(uint32_t r[4], uint32_t addr) {
    asm volatile("ldmatrix.sync.aligned.m8n8.x4.trans.shared.b16 {%0,%1,%2,%3}, [%4];"
                 : "=r"(r[0]), "=r"(r[1]), "=r"(r[2]), "=r"(r[3]) : "r"(addr));
}
__device__ __forceinline__ void mma_bf16(float c[4], const uint32_t a[4],
                                         uint32_t b0, uint32_t b1) {
    asm volatile(
        "mma.sync.aligned.m16n8k16.row.col.f32.bf16.bf16.f32 "
        "{%0,%1,%2,%3}, {%4,%5,%6,%7}, {%8,%9}, {%0,%1,%2,%3};"
        : "+f"(c[0]), "+f"(c[1]), "+f"(c[2]), "+f"(c[3])
        : "r"(a[0]), "r"(a[1]), "r"(a[2]), "r"(a[3]), "r"(b0), "r"(b1));
}
// split f into bf16 hi/lo, packed bf16x2
__device__ __forceinline__ void split2(float f0, float f1,
                                       uint32_t& hi2, uint32_t& lo2) {
    __nv_bfloat16 h0 = __float2bfloat16(f0);
    __nv_bfloat16 h1 = __float2bfloat16(f1);
    __nv_bfloat16 l0 = __float2bfloat16(f0 - __bfloat162float(h0));
    __nv_bfloat16 l1 = __float2bfloat16(f1 - __bfloat162float(h1));
    __nv_bfloat162 h = __halves2bfloat162(h0, h1);
    __nv_bfloat162 l = __halves2bfloat162(l0, l1);
    hi2 = *reinterpret_cast<uint32_t*>(&h);
    lo2 = *reinterpret_cast<uint32_t*>(&l);
}

__global__ void __launch_bounds__(128)
gemm_hmma_kernel(const float* __restrict__ W, const float* __restrict__ bias,
                 float* __restrict__ out) {
    __shared__ __align__(16) uint16_t sAh[GBM * PA];
    __shared__ __align__(16) uint16_t sAl[GBM * PA];
    __shared__ __align__(16) uint16_t sBh[GBK * PB];
    __shared__ __align__(16) uint16_t sBl[GBK * PB];

    const int tid  = threadIdx.x;
    const int warp = tid >> 5;
    const int lane = tid & 31;
    const int wm   = warp >> 1;          // 0..1
    const int wn   = warp & 1;           // 0..1
    const int r0   = blockIdx.y * GBM;   // 0..992
    const int c0   = blockIdx.x * GBN;   // 0..640

    // ldmatrix lane base addresses (bytes)
    const uint32_t aH = smem_u32(sAh), aL = smem_u32(sAl);
    const uint32_t bH = smem_u32(sBh), bL = smem_u32(sBl);
    const int mat = lane >> 3, mr = lane & 7;
    const uint32_t aOff =
        (uint32_t)((wm * 16 + (mat & 1) * 8 + mr) * PA + (mat >> 1) * 8) * 2;
    const int bk  = lane & 15;
    const int bn8 = lane >> 4;           // 0/1
    const uint32_t bOff0 = (uint32_t)(bk * PB + wn * 32 + bn8 * 8) * 2;
    const uint32_t bOff1 = bOff0 + 16 * 2;

    float acc[4][4];
#pragma unroll
    for (int i = 0; i < 4; i++)
#pragma unroll
        for (int j = 0; j < 4; j++) acc[i][j] = 0.f;

    for (int s = 0; s < NSTAGE; s++) {
        const int k0 = s * GBK;
        if (s > 0) __syncthreads();      // previous stage fully consumed

        // ---- fill A: 32 rows x 64 k (float4 from g_V — 768 stride, aligned) ----
#pragma unroll
        for (int g = 0; g < 4; g++) {
            int flat = tid + g * 128;        // 0..511 float4 slots
            int m  = flat >> 4;              // 0..31
            int kk = (flat & 15) * 4;        // 0..60
            float4 v = *reinterpret_cast<const float4*>(
                &g_V[(size_t)(r0 + m) * CDIM + k0 + kk]);
            uint32_t h0, l0, h1, l1;
            split2(v.x, v.y, h0, l0);
            split2(v.z, v.w, h1, l1);
            uint32_t off = (uint32_t)(m * PA + kk);
            *reinterpret_cast<uint2*>(&sAh[off]) = make_uint2(h0, h1);
            *reinterpret_cast<uint2*>(&sAl[off]) = make_uint2(l0, l1);
        }
        // ---- fill B: 64 k-rows x 64 n — SCALAR loads (stride 701 is odd) ----
#pragma unroll
        for (int g = 0; g < 8; g++) {
            int flat = tid + g * 128;        // 0..1023 quad slots
            int kk = flat >> 4;              // 0..63
            int nn = (flat & 15) * 4;        // 0..60
            const float* wr = &W[(size_t)(k0 + kk) * NCLS + c0 + nn];
            float v0 = (c0 + nn + 0 < NCLS) ? wr[0] : 0.f;
            float v1 = (c0 + nn + 1 < NCLS) ? wr[1] : 0.f;
            float v2 = (c0 + nn + 2 < NCLS) ? wr[2] : 0.f;
            float v3 = (c0 + nn + 3 < NCLS) ? wr[3] : 0.f;
            uint32_t h0, l0, h1, l1;
            split2(v0, v1, h0, l0);
            split2(v2, v3, h1, l1);
            uint32_t off = (uint32_t)(kk * PB + nn);
            *reinterpret_cast<uint2*>(&sBh[off]) = make_uint2(h0, h1);
            *reinterpret_cast<uint2*>(&sBl[off]) = make_uint2(l0, l1);
        }
        __syncthreads();

        // ---- 4 k16 steps ----
#pragma unroll
        for (int ks = 0; ks < 4; ks++) {
            uint32_t ah[4], al[4];
            ldm_x4(ah, aH + aOff + ks * 32);
            ldm_x4(al, aL + aOff + ks * 32);
            uint32_t bh0[4], bh1[4], bl0[4], bl1[4];
            const uint32_t kByte = (uint32_t)(ks * 16 * PB * 2);
            ldm_x4_t(bh0, bH + bOff0 + kByte);
            ldm_x4_t(bh1, bH + bOff1 + kByte);
            ldm_x4_t(bl0, bL + bOff0 + kByte);
            ldm_x4_t(bl1, bL + bOff1 + kByte);

            // acc[nb]: nb = n8-block 0..3 (cols wn*32 + nb*8)
            mma_bf16(acc[0], ah, bh0[0], bh0[1]);
            mma_bf16(acc[1], ah, bh0[2], bh0[3]);
            mma_bf16(acc[2], ah, bh1[0], bh1[1]);
            mma_bf16(acc[3], ah, bh1[2], bh1[3]);

            mma_bf16(acc[0], ah, bl0[0], bl0[1]);
            mma_bf16(acc[1], ah, bl0[2], bl0[3]);
            mma_bf16(acc[2], ah, bl1[0], bl1[1]);
            mma_bf16(acc[3], ah, bl1[2], bl1[3]);

            mma_bf16(acc[0], al, bh0[0], bh0[1]);
            mma_bf16(acc[1], al, bh0[2], bh0[3]);
            mma_bf16(acc[2], al, bh1[0], bh1[1]);
            mma_bf16(acc[3], al, bh1[2], bh1[3]);
        }
    }

    // ---- epilogue: c-frag: c0:(g,t2) c1:(g,t2+1) c2:(g+8,t2) c3:(g+8,t2+1)
    const int rA = r0 + wm * 16 + (lane >> 2);
    const int rB = rA + 8;
    const int cBase = c0 + wn * 32 + (lane & 3) * 2;
#pragma unroll
    for (int nb = 0; nb < 4; nb++) {
        int c = cBase + nb * 8;
        if (c < NCLS) {
            float bb = bias[c];
            out[(size_t)rA * NCLS + c] = acc[nb][0] + bb;
            out[(size_t)rB * NCLS + c] = acc[nb][2] + bb;
        }
        if (c + 1 < NCLS) {
            float bb = bias[c + 1];
            out[(size_t)rA * NCLS + c + 1] = acc[nb][1] + bb;
            out[(size_t)rB * NCLS + c + 1] = acc[nb][3] + bb;
        }
    }
}

// ============================================================================
extern "C" void kernel_launch(void* const* d_in, const int* in_sizes, int n_in,
                              void* d_out, int out_size) {
    const float* x1 = nullptr;
    const float* x2 = nullptr;
    const float* W  = nullptr;
    const float* bb = nullptr;
    for (int i = 0; i < n_in; i++) {
        if (in_sizes[i] == BATCH * NTOK * CDIM) {
            if (!x1) x1 = (const float*)d_in[i];
            else if (!x2) x2 = (const float*)d_in[i];
        } else if (in_sizes[i] == CDIM * NCLS) {
            W = (const float*)d_in[i];
        } else if (in_sizes[i] == NCLS) {
            bb = (const float*)d_in[i];
        }
    }
    float* out = (float*)d_out;

    dim3 g1(BATCH, 2);
    sgm_kernel<<<g1, 256>>>(x1, x2);

    dim3 g2((NCLS + GBN - 1) / GBN, (4 * BATCH) / GBM);  // 11 x 32 = 352
    gemm_hmma_kernel<<<g2, 128>>>(W, bb, out);
}

// round 6
// speedup vs baseline: 1.7505x; 1.4344x over previous
#include <cuda_runtime.h>
#include <cuda_bf16.h>
#include <math.h>
#include <stdint.h>

#define NTOK   196
#define CDIM   768
#define BATCH  256
#define NCLS   701
#define NPAD   704      // NCLS padded to 64-multiple

// bf16 hi/lo pre-split operands (device scratch; no allocation)
__device__ __nv_bfloat16 g_Ah[4 * BATCH * CDIM];   // [1024][768]
__device__ __nv_bfloat16 g_Al[4 * BATCH * CDIM];
__device__ __nv_bfloat16 g_Wh[CDIM * NPAD];        // [768][704]
__device__ __nv_bfloat16 g_Wl[CDIM * NPAD];

__device__ __forceinline__ uint32_t smem_u32(const void* p) {
    uint32_t a;
    asm("{ .reg .u64 t; cvta.to.shared.u64 t, %1; cvt.u32.u64 %0, t; }"
        : "=r"(a) : "l"(p));
    return a;
}
// split (f0,f1) into packed bf16x2 hi and lo
__device__ __forceinline__ void split2(float f0, float f1,
                                       uint32_t& hi2, uint32_t& lo2) {
    __nv_bfloat16 h0 = __float2bfloat16(f0);
    __nv_bfloat16 h1 = __float2bfloat16(f1);
    __nv_bfloat16 l0 = __float2bfloat16(f0 - __bfloat162float(h0));
    __nv_bfloat16 l1 = __float2bfloat16(f1 - __bfloat162float(h1));
    __nv_bfloat162 h = __halves2bfloat162(h0, h1);
    __nv_bfloat162 l = __halves2bfloat162(l0, l1);
    hi2 = *reinterpret_cast<uint32_t*>(&h);
    lo2 = *reinterpret_cast<uint32_t*>(&l);
}

// ============================================================================
// Kernel 0: split W -> g_Wh/g_Wl ([k][704], zero-padded cols). Coalesced.
// ============================================================================
__global__ void __launch_bounds__(256)
wsplit_kernel(const float* __restrict__ W) {
    int idx = blockIdx.x * 256 + threadIdx.x;     // 0 .. 768*704-1
    if (idx >= CDIM * NPAD) return;
    int k = idx / NPAD;
    int n = idx - k * NPAD;
    float v = (n < NCLS) ? W[(size_t)k * NCLS + n] : 0.f;
    __nv_bfloat16 h = __float2bfloat16(v);
    g_Wh[idx] = h;
    g_Wl[idx] = __float2bfloat16(v - __bfloat162float(h));
}

// ============================================================================
// Kernel 1: fused SGM per (tensor, sample). Writes bf16 hi/lo mean rows.
// ============================================================================
__global__ void __launch_bounds__(256)
sgm_kernel(const float* __restrict__ x1, const float* __restrict__ x2) {
    const int b      = blockIdx.x;
    const int tensor = blockIdx.y;
    const float* x = (tensor == 0 ? x1 : x2) + (size_t)b * NTOK * CDIM;

    __shared__ float sT[8][CDIM];
    __shared__ float sTtot[CDIM];
    __shared__ float sM[NTOK];
    __shared__ float sSorted[NTOK];
    __shared__ float sVal[256];
    __shared__ int   sIdx[256];
    __shared__ int   sList[112];
    __shared__ int   sCnt;
    __shared__ float sMnMx[2];

    const int tid  = threadIdx.x;
    const int warp = tid >> 5;
    const int lane = tid & 31;

    float tacc[24];
#pragma unroll
    for (int i = 0; i < 24; i++) tacc[i] = 0.f;

    for (int n = warp; n < NTOK; n += 8) {
        const float4* row = reinterpret_cast<const float4*>(x + (size_t)n * CDIM);
        float msum = 0.f;
#pragma unroll
        for (int i = 0; i < 6; i++) {
            float4 v = row[lane + 32 * i];
            tacc[4*i+0] += v.x; tacc[4*i+1] += v.y;
            tacc[4*i+2] += v.z; tacc[4*i+3] += v.w;
            msum += (v.x + v.y) + (v.z + v.w);
        }
#pragma unroll
        for (int off = 16; off > 0; off >>= 1)
            msum += __shfl_down_sync(0xffffffffu, msum, off);
        if (lane == 0) sM[n] = msum;
    }
    {
        float4* st = reinterpret_cast<float4*>(&sT[warp][0]);
#pragma unroll
        for (int i = 0; i < 6; i++)
            st[lane + 32 * i] = make_float4(tacc[4*i], tacc[4*i+1], tacc[4*i+2], tacc[4*i+3]);
    }
    if (tid == 0) sCnt = 0;
    __syncthreads();

    if (tid < 192) {
        float4 t = make_float4(0.f, 0.f, 0.f, 0.f);
#pragma unroll
        for (int w = 0; w < 8; w++) {
            float4 v = reinterpret_cast<float4*>(&sT[w][0])[tid];
            t.x += v.x; t.y += v.y; t.z += v.z; t.w += v.w;
        }
        reinterpret_cast<float4*>(sTtot)[tid] = t;
    }
    __syncthreads();

    sVal[tid] = (tid < NTOK) ? sM[tid] : 3.4e38f;
    __syncthreads();
    for (int s = 128; s > 0; s >>= 1) {
        if (tid < s) sVal[tid] = fminf(sVal[tid], sVal[tid + s]);
        __syncthreads();
    }
    if (tid == 0) sMnMx[0] = sVal[0];
    __syncthreads();
    sVal[tid] = (tid < NTOK) ? sM[tid] : -3.4e38f;
    __syncthreads();
    for (int s = 128; s > 0; s >>= 1) {
        if (tid < s) sVal[tid] = fmaxf(sVal[tid], sVal[tid + s]);
        __syncthreads();
    }
    if (tid == 0) sMnMx[1] = sVal[0];
    __syncthreads();

    const float mn  = sMnMx[0];
    const float mx  = sMnMx[1];
    const float inv = 1.f / (mx - mn);

    float myMn = 0.f;
    __syncthreads();
    if (tid < NTOK) myMn = (sM[tid] - mn) * inv;
    sVal[tid] = myMn;
    __syncthreads();

    int myrank = 0;
    if (tid < NTOK) {
        int r = 0;
        for (int m = 0; m < NTOK; m++) {
            float o = sVal[m];
            r += (o < myMn) || (o == myMn && m < tid);
        }
        myrank = r;
        sSorted[r] = myMn;
    }
    __syncthreads();

    float dv = -1.f;
    if (tid < NTOK - 1) {
        float s0 = sSorted[tid];
        dv = (s0 == 0.f) ? 0.f : (sSorted[tid + 1] - s0);
    }
    sVal[tid] = dv;
    sIdx[tid] = tid;
    __syncthreads();
    for (int s = 128; s > 0; s >>= 1) {
        if (tid < s) {
            float v2 = sVal[tid + s]; int i2 = sIdx[tid + s];
            if (v2 > sVal[tid] || (v2 == sVal[tid] && i2 < sIdx[tid])) {
                sVal[tid] = v2; sIdx[tid] = i2;
            }
        }
        __syncthreads();
    }
    const int  k         = sIdx[0];
    const bool smallIsFg = (k <= NTOK / 2);

    if (tid < NTOK) {
        bool inSmall = smallIsFg ? (myrank < k) : (myrank >= k);
        if (inSmall) {
            int p = atomicAdd(&sCnt, 1);
            sList[p] = tid;
        }
    }
    __syncthreads();
    const int cnt = sCnt;

#pragma unroll
    for (int i = 0; i < 24; i++) tacc[i] = 0.f;
    for (int j = warp; j < cnt; j += 8) {
        int nn = sList[j];
        const float4* row = reinterpret_cast<const float4*>(x + (size_t)nn * CDIM);
#pragma unroll
        for (int i = 0; i < 6; i++) {
            float4 v = row[lane + 32 * i];
            tacc[4*i+0] += v.x; tacc[4*i+1] += v.y;
            tacc[4*i+2] += v.z; tacc[4*i+3] += v.w;
        }
    }
    {
        float4* st = reinterpret_cast<float4*>(&sT[warp][0]);
#pragma unroll
        for (int i = 0; i < 6; i++)
            st[lane + 32 * i] = make_float4(tacc[4*i], tacc[4*i+1], tacc[4*i+2], tacc[4*i+3]);
    }
    __syncthreads();

    if (tid < 192) {
        float4 S = make_float4(0.f, 0.f, 0.f, 0.f);
#pragma unroll
        for (int w = 0; w < 8; w++) {
            float4 v = reinterpret_cast<float4*>(&sT[w][0])[tid];
            S.x += v.x; S.y += v.y; S.z += v.z; S.w += v.w;
        }
        float4 T = reinterpret_cast<float4*>(sTtot)[tid];

        float4 fgs, bgs;
        if (smallIsFg) {
            fgs = S;
            bgs = make_float4(T.x - S.x, T.y - S.y, T.z - S.z, T.w - S.w);
        } else {
            bgs = S;
            fgs = make_float4(T.x - S.x, T.y - S.y, T.z - S.z, T.w - S.w);
        }
        const float fgc = fmaxf((float)k, 1.f);
        const float bgc = fmaxf((float)(NTOK - k), 1.f);
        float4 fg = make_float4(fgs.x / fgc, fgs.y / fgc, fgs.z / fgc, fgs.w / fgc);
        float4 bg = make_float4(bgs.x / bgc, bgs.y / bgc, bgs.z / bgc, bgs.w / bgc);

        const size_t rowBg = (size_t)((tensor * 2 + 0) * BATCH + b) * CDIM + tid * 4;
        const size_t rowFg = (size_t)((tensor * 2 + 1) * BATCH + b) * CDIM + tid * 4;
        uint32_t h01, l01, h23, l23;
        split2(bg.x, bg.y, h01, l01);
        split2(bg.z, bg.w, h23, l23);
        *reinterpret_cast<uint2*>(&g_Ah[rowBg]) = make_uint2(h01, h23);
        *reinterpret_cast<uint2*>(&g_Al[rowBg]) = make_uint2(l01, l23);
        split2(fg.x, fg.y, h01, l01);
        split2(fg.z, fg.w, h23, l23);
        *reinterpret_cast<uint2*>(&g_Ah[rowFg]) = make_uint2(h01, h23);
        *reinterpret_cast<uint2*>(&g_Al[rowFg]) = make_uint2(l01, l23);
    }
}

// ============================================================================
// Kernel 2: HMMA GEMM on pre-split bf16, cp.async double-buffered.
//   out[1024,701] = (Ah+Al)@(Wh+Wl) + bias  (3 terms, fp32 accum)
// Tile 64x64, 256 threads (4x2 warps, warp tile 16x32), BK=64, 12 stages.
// ============================================================================
#define GBM 64
#define GBN 64
#define GBK 64
#define PITCH 72                 // bf16 pitch (144 B rows: 16B-aligned, 4r%32 banks)
#define ROWB (PITCH * 2)         // 144
#define NSTAGE (CDIM / GBK)      // 12
#define OFF_AH 0
#define OFF_AL 9216
#define OFF_BH 18432
#define OFF_BL 27648
#define BUFSZ  36864
#define SMEM_TOTAL (2 * BUFSZ)   // 73728

__device__ __forceinline__ void cp16(uint32_t dst, const void* src) {
    asm volatile("cp.async.cg.shared.global [%0], [%1], 16;" :: "r"(dst), "l"(src));
}
__device__ __forceinline__ void ldm_x4(uint32_t r[4], uint32_t addr) {
    asm volatile("ldmatrix.sync.aligned.m8n8.x4.shared.b16 {%0,%1,%2,%3}, [%4];"
                 : "=r"(r[0]), "=r"(r[1]), "=r"(r[2]), "=r"(r[3]) : "r"(addr));
}
__device__ __forceinline__ void ldm_x4_t(uint32_t r[4], uint32_t addr) {
    asm volatile("ldmatrix.sync.aligned.m8n8.x4.trans.shared.b16 {%0,%1,%2,%3}, [%4];"
                 : "=r"(r[0]), "=r"(r[1]), "=r"(r[2]), "=r"(r[3]) : "r"(addr));
}
__device__ __forceinline__ void mma_bf16(float c[4], const uint32_t a[4],
                                         uint32_t b0, uint32_t b1) {
    asm volatile(
        "mma.sync.aligned.m16n8k16.row.col.f32.bf16.bf16.f32 "
        "{%0,%1,%2,%3}, {%4,%5,%6,%7}, {%8,%9}, {%0,%1,%2,%3};"
        : "+f"(c[0]), "+f"(c[1]), "+f"(c[2]), "+f"(c[3])
        : "r"(a[0]), "r"(a[1]), "r"(a[2]), "r"(a[3]), "r"(b0), "r"(b1));
}

__device__ __forceinline__ void issue_stage(uint32_t sbase, int buf, int s,
                                            int r0, int c0, int tid) {
    const int k0 = s * GBK;
    const uint32_t base = sbase + (uint32_t)buf * BUFSZ;
#pragma unroll
    for (int i = 0; i < 2; i++) {
        int c  = tid + i * 256;          // 0..511
        int m  = c >> 3;                 // 0..63 (A row / B k-row)
        int ch = c & 7;                  // 16B chunk in row
        uint32_t so = (uint32_t)(m * ROWB + ch * 16);
        const size_t aoff = (size_t)(r0 + m) * CDIM + k0 + ch * 8;
        const size_t boff = (size_t)(k0 + m) * NPAD + c0 + ch * 8;
        cp16(base + OFF_AH + so, g_Ah + aoff);
        cp16(base + OFF_AL + so, g_Al + aoff);
        cp16(base + OFF_BH + so, g_Wh + boff);
        cp16(base + OFF_BL + so, g_Wl + boff);
    }
}

__global__ void __launch_bounds__(256)
gemm_hmma_kernel(const float* __restrict__ bias, float* __restrict__ out) {
    extern __shared__ __align__(16) char smem[];
    const uint32_t sbase = smem_u32(smem);
    const int tid  = threadIdx.x;
    const int warp = tid >> 5;
    const int lane = tid & 31;
    const int wm   = warp & 3;           // 0..3  -> m offset wm*16
    const int wn   = warp >> 2;          // 0..1  -> n offset wn*32
    const int r0   = blockIdx.y * GBM;
    const int c0   = blockIdx.x * GBN;

    const int mat = lane >> 3, mr = lane & 7;
    const uint32_t aOff =
        (uint32_t)((wm * 16 + (mat & 1) * 8 + mr) * ROWB + (mat >> 1) * 16);
    const int bk  = lane & 15;
    const int bn8 = lane >> 4;
    const uint32_t bOff0 = (uint32_t)(bk * ROWB + (wn * 32 + bn8 * 8) * 2);
    const uint32_t bOff1 = bOff0 + 32;

    float acc[4][4];
#pragma unroll
    for (int i = 0; i < 4; i++)
#pragma unroll
        for (int j = 0; j < 4; j++) acc[i][j] = 0.f;

    issue_stage(sbase, 0, 0, r0, c0, tid);
    asm volatile("cp.async.commit_group;" ::: "memory");

    for (int s = 0; s < NSTAGE; s++) {
        const int buf = s & 1;
        if (s + 1 < NSTAGE) {
            issue_stage(sbase, buf ^ 1, s + 1, r0, c0, tid);
            asm volatile("cp.async.commit_group;" ::: "memory");
            asm volatile("cp.async.wait_group 1;" ::: "memory");
        } else {
            asm volatile("cp.async.wait_group 0;" ::: "memory");
        }
        __syncthreads();

        const uint32_t bb = sbase + (uint32_t)buf * BUFSZ;
        const uint32_t aHb = bb + OFF_AH + aOff;
        const uint32_t aLb = bb + OFF_AL + aOff;
        const uint32_t bHb = bb + OFF_BH;
        const uint32_t bLb = bb + OFF_BL;

#pragma unroll
        for (int ks = 0; ks < 4; ks++) {
            uint32_t ah[4], al[4];
            ldm_x4(ah, aHb + ks * 32);
            ldm_x4(al, aLb + ks * 32);
            uint32_t bh0[4], bh1[4], bl0[4], bl1[4];
            const uint32_t kByte = (uint32_t)(ks * 16 * ROWB);
            ldm_x4_t(bh0, bHb + bOff0 + kByte);
            ldm_x4_t(bh1, bHb + bOff1 + kByte);
            ldm_x4_t(bl0, bLb + bOff0 + kByte);
            ldm_x4_t(bl1, bLb + bOff1 + kByte);

            mma_bf16(acc[0], ah, bh0[0], bh0[1]);
            mma_bf16(acc[1], ah, bh0[2], bh0[3]);
            mma_bf16(acc[2], ah, bh1[0], bh1[1]);
            mma_bf16(acc[3], ah, bh1[2], bh1[3]);

            mma_bf16(acc[0], ah, bl0[0], bl0[1]);
            mma_bf16(acc[1], ah, bl0[2], bl0[3]);
            mma_bf16(acc[2], ah, bl1[0], bl1[1]);
            mma_bf16(acc[3], ah, bl1[2], bl1[3]);

            mma_bf16(acc[0], al, bh0[0], bh0[1]);
            mma_bf16(acc[1], al, bh0[2], bh0[3]);
            mma_bf16(acc[2], al, bh1[0], bh1[1]);
            mma_bf16(acc[3], al, bh1[2], bh1[3]);
        }
        __syncthreads();
    }

    // epilogue: c-frag: c0:(g,t2) c1:(g,t2+1) c2:(g+8,t2) c3:(g+8,t2+1)
    const int rA = r0 + wm * 16 + (lane >> 2);
    const int rB = rA + 8;
    const int cBase = c0 + wn * 32 + (lane & 3) * 2;
#pragma unroll
    for (int nb = 0; nb < 4; nb++) {
        int c = cBase + nb * 8;
        if (c < NCLS) {
            float bv = bias[c];
            out[(size_t)rA * NCLS + c] = acc[nb][0] + bv;
            out[(size_t)rB * NCLS + c] = acc[nb][2] + bv;
        }
        if (c + 1 < NCLS) {
            float bv = bias[c + 1];
            out[(size_t)rA * NCLS + c + 1] = acc[nb][1] + bv;
            out[(size_t)rB * NCLS + c + 1] = acc[nb][3] + bv;
        }
    }
}

// ============================================================================
extern "C" void kernel_launch(void* const* d_in, const int* in_sizes, int n_in,
                              void* d_out, int out_size) {
    const float* x1 = nullptr;
    const float* x2 = nullptr;
    const float* W  = nullptr;
    const float* bb = nullptr;
    for (int i = 0; i < n_in; i++) {
        if (in_sizes[i] == BATCH * NTOK * CDIM) {
            if (!x1) x1 = (const float*)d_in[i];
            else if (!x2) x2 = (const float*)d_in[i];
        } else if (in_sizes[i] == CDIM * NCLS) {
            W = (const float*)d_in[i];
        } else if (in_sizes[i] == NCLS) {
            bb = (const float*)d_in[i];
        }
    }
    float* out = (float*)d_out;

    wsplit_kernel<<<(CDIM * NPAD + 255) / 256, 256>>>(W);

    dim3 g1(BATCH, 2);
    sgm_kernel<<<g1, 256>>>(x1, x2);

    static bool attr_done = false;
    if (!attr_done) {
        cudaFuncSetAttribute(gemm_hmma_kernel,
                             cudaFuncAttributeMaxDynamicSharedMemorySize, SMEM_TOTAL);
        attr_done = true;
    }
    dim3 g2(NPAD / GBN, (4 * BATCH) / GBM);   // 11 x 16 = 176
    gemm_hmma_kernel<<<g2, 256, SMEM_TOTAL>>>(bb, out);
}

// round 7
// speedup vs baseline: 1.8079x; 1.0328x over previous
#include <cuda_runtime.h>
#include <cuda_bf16.h>
#include <math.h>
#include <stdint.h>

#define NTOK   196
#define CDIM   768
#define BATCH  256
#define NCLS   701
#define NPAD   704      // NCLS padded to 64-multiple

// bf16 hi/lo pre-split operands (device scratch; no allocation)
__device__ __nv_bfloat16 g_Ah[4 * BATCH * CDIM];   // [1024][768]
__device__ __nv_bfloat16 g_Al[4 * BATCH * CDIM];
__device__ __nv_bfloat16 g_Wh[CDIM * NPAD];        // [768][704]
__device__ __nv_bfloat16 g_Wl[CDIM * NPAD];

__device__ __forceinline__ uint32_t smem_u32(const void* p) {
    uint32_t a;
    asm("{ .reg .u64 t; cvta.to.shared.u64 t, %1; cvt.u32.u64 %0, t; }"
        : "=r"(a) : "l"(p));
    return a;
}
// split (f0,f1) into packed bf16x2 hi and lo
__device__ __forceinline__ void split2(float f0, float f1,
                                       uint32_t& hi2, uint32_t& lo2) {
    __nv_bfloat16 h0 = __float2bfloat16(f0);
    __nv_bfloat16 h1 = __float2bfloat16(f1);
    __nv_bfloat16 l0 = __float2bfloat16(f0 - __bfloat162float(h0));
    __nv_bfloat16 l1 = __float2bfloat16(f1 - __bfloat162float(h1));
    __nv_bfloat162 h = __halves2bfloat162(h0, h1);
    __nv_bfloat162 l = __halves2bfloat162(l0, l1);
    hi2 = *reinterpret_cast<uint32_t*>(&h);
    lo2 = *reinterpret_cast<uint32_t*>(&l);
}

// ============================================================================
// Kernel 1: fused SGM per (tensor, sample)  [gridDim.y == 0,1]
//           + W hi/lo split                 [gridDim.y == 2]
// ============================================================================
__global__ void __launch_bounds__(256)
sgm_kernel(const float* __restrict__ x1, const float* __restrict__ x2,
           const float* __restrict__ W) {
    const int tid  = threadIdx.x;

    // ---------------- W-split branch (independent work, overlapped) --------
    if (blockIdx.y == 2) {
        const int tot = CDIM * NPAD;
        for (int idx = blockIdx.x * 256 + tid; idx < tot; idx += BATCH * 256) {
            int k = idx / NPAD;
            int n = idx - k * NPAD;
            float v = (n < NCLS) ? W[(size_t)k * NCLS + n] : 0.f;
            __nv_bfloat16 h = __float2bfloat16(v);
            g_Wh[idx] = h;
            g_Wl[idx] = __float2bfloat16(v - __bfloat162float(h));
        }
        return;
    }

    const int b      = blockIdx.x;
    const int tensor = blockIdx.y;
    const float* x = (tensor == 0 ? x1 : x2) + (size_t)b * NTOK * CDIM;

    __shared__ float sT[8][CDIM];
    __shared__ float sTtot[CDIM];
    __shared__ float sM[NTOK];
    __shared__ float sSorted[NTOK];
    __shared__ float sVal[256];
    __shared__ int   sIdx[256];
    __shared__ int   sList[112];
    __shared__ int   sCnt;
    __shared__ float sMnMx[2];

    const int warp = tid >> 5;
    const int lane = tid & 31;

    float tacc[24];
#pragma unroll
    for (int i = 0; i < 24; i++) tacc[i] = 0.f;

    for (int n = warp; n < NTOK; n += 8) {
        const float4* row = reinterpret_cast<const float4*>(x + (size_t)n * CDIM);
        float msum = 0.f;
#pragma unroll
        for (int i = 0; i < 6; i++) {
            float4 v = row[lane + 32 * i];
            tacc[4*i+0] += v.x; tacc[4*i+1] += v.y;
            tacc[4*i+2] += v.z; tacc[4*i+3] += v.w;
            msum += (v.x + v.y) + (v.z + v.w);
        }
#pragma unroll
        for (int off = 16; off > 0; off >>= 1)
            msum += __shfl_down_sync(0xffffffffu, msum, off);
        if (lane == 0) sM[n] = msum;
    }
    {
        float4* st = reinterpret_cast<float4*>(&sT[warp][0]);
#pragma unroll
        for (int i = 0; i < 6; i++)
            st[lane + 32 * i] = make_float4(tacc[4*i], tacc[4*i+1], tacc[4*i+2], tacc[4*i+3]);
    }
    if (tid == 0) sCnt = 0;
    __syncthreads();

    if (tid < 192) {
        float4 t = make_float4(0.f, 0.f, 0.f, 0.f);
#pragma unroll
        for (int w = 0; w < 8; w++) {
            float4 v = reinterpret_cast<float4*>(&sT[w][0])[tid];
            t.x += v.x; t.y += v.y; t.z += v.z; t.w += v.w;
        }
        reinterpret_cast<float4*>(sTtot)[tid] = t;
    }
    __syncthreads();

    // min and max in a single reduction pass (sVal = min, sIdx-area reused via
    // a second float buffer overlaid on sSorted for max)
    sVal[tid]    = (tid < NTOK) ? sM[tid] : 3.4e38f;
    sSorted[tid < NTOK ? tid : 0] = 0.f;  // placeholder (sSorted rewritten later)
    __shared__ float sMax[256];
    sMax[tid] = (tid < NTOK) ? sM[tid] : -3.4e38f;
    __syncthreads();
    for (int s = 128; s > 0; s >>= 1) {
        if (tid < s) {
            sVal[tid] = fminf(sVal[tid], sVal[tid + s]);
            sMax[tid] = fmaxf(sMax[tid], sMax[tid + s]);
        }
        __syncthreads();
    }
    if (tid == 0) { sMnMx[0] = sVal[0]; sMnMx[1] = sMax[0]; }
    __syncthreads();

    const float mn  = sMnMx[0];
    const float mx  = sMnMx[1];
    const float inv = 1.f / (mx - mn);

    float myMn = 0.f;
    if (tid < NTOK) myMn = (sM[tid] - mn) * inv;
    sVal[tid] = myMn;
    __syncthreads();

    int myrank = 0;
    if (tid < NTOK) {
        int r = 0;
#pragma unroll 4
        for (int m = 0; m < NTOK; m++) {
            float o = sVal[m];
            r += (o < myMn) || (o == myMn && m < tid);
        }
        myrank = r;
        sSorted[r] = myMn;
    }
    __syncthreads();

    float dv = -1.f;
    if (tid < NTOK - 1) {
        float s0 = sSorted[tid];
        dv = (s0 == 0.f) ? 0.f : (sSorted[tid + 1] - s0);
    }
    sVal[tid] = dv;
    sIdx[tid] = tid;
    __syncthreads();
    for (int s = 128; s > 0; s >>= 1) {
        if (tid < s) {
            float v2 = sVal[tid + s]; int i2 = sIdx[tid + s];
            if (v2 > sVal[tid] || (v2 == sVal[tid] && i2 < sIdx[tid])) {
                sVal[tid] = v2; sIdx[tid] = i2;
            }
        }
        __syncthreads();
    }
    const int  k         = sIdx[0];
    const bool smallIsFg = (k <= NTOK / 2);

    if (tid < NTOK) {
        bool inSmall = smallIsFg ? (myrank < k) : (myrank >= k);
        if (inSmall) {
            int p = atomicAdd(&sCnt, 1);
            sList[p] = tid;
        }
    }
    __syncthreads();
    const int cnt = sCnt;

#pragma unroll
    for (int i = 0; i < 24; i++) tacc[i] = 0.f;
    for (int j = warp; j < cnt; j += 8) {
        int nn = sList[j];
        const float4* row = reinterpret_cast<const float4*>(x + (size_t)nn * CDIM);
#pragma unroll
        for (int i = 0; i < 6; i++) {
            float4 v = row[lane + 32 * i];
            tacc[4*i+0] += v.x; tacc[4*i+1] += v.y;
            tacc[4*i+2] += v.z; tacc[4*i+3] += v.w;
        }
    }
    {
        float4* st = reinterpret_cast<float4*>(&sT[warp][0]);
#pragma unroll
        for (int i = 0; i < 6; i++)
            st[lane + 32 * i] = make_float4(tacc[4*i], tacc[4*i+1], tacc[4*i+2], tacc[4*i+3]);
    }
    __syncthreads();

    if (tid < 192) {
        float4 S = make_float4(0.f, 0.f, 0.f, 0.f);
#pragma unroll
        for (int w = 0; w < 8; w++) {
            float4 v = reinterpret_cast<float4*>(&sT[w][0])[tid];
            S.x += v.x; S.y += v.y; S.z += v.z; S.w += v.w;
        }
        float4 T = reinterpret_cast<float4*>(sTtot)[tid];

        float4 fgs, bgs;
        if (smallIsFg) {
            fgs = S;
            bgs = make_float4(T.x - S.x, T.y - S.y, T.z - S.z, T.w - S.w);
        } else {
            bgs = S;
            fgs = make_float4(T.x - S.x, T.y - S.y, T.z - S.z, T.w - S.w);
        }
        const float fgc = fmaxf((float)k, 1.f);
        const float bgc = fmaxf((float)(NTOK - k), 1.f);
        float4 fg = make_float4(fgs.x / fgc, fgs.y / fgc, fgs.z / fgc, fgs.w / fgc);
        float4 bg = make_float4(bgs.x / bgc, bgs.y / bgc, bgs.z / bgc, bgs.w / bgc);

        const size_t rowBg = (size_t)((tensor * 2 + 0) * BATCH + b) * CDIM + tid * 4;
        const size_t rowFg = (size_t)((tensor * 2 + 1) * BATCH + b) * CDIM + tid * 4;
        uint32_t h01, l01, h23, l23;
        split2(bg.x, bg.y, h01, l01);
        split2(bg.z, bg.w, h23, l23);
        *reinterpret_cast<uint2*>(&g_Ah[rowBg]) = make_uint2(h01, h23);
        *reinterpret_cast<uint2*>(&g_Al[rowBg]) = make_uint2(l01, l23);
        split2(fg.x, fg.y, h01, l01);
        split2(fg.z, fg.w, h23, l23);
        *reinterpret_cast<uint2*>(&g_Ah[rowFg]) = make_uint2(h01, h23);
        *reinterpret_cast<uint2*>(&g_Al[rowFg]) = make_uint2(l01, l23);
    }
}

// ============================================================================
// Kernel 2: HMMA GEMM on pre-split bf16, cp.async double-buffered.
// Tile 32x64, 256 threads (2x4 warps, warp tile 16x16), BK=64, 12 stages.
// Grid 11 x 32 = 352 blocks, ~55KB smem -> 4 resident blocks/SM.
// ============================================================================
#define GBM 32
#define GBN 64
#define GBK 64
#define PITCH 72                 // bf16 pitch (144 B rows)
#define ROWB (PITCH * 2)         // 144
#define NSTAGE (CDIM / GBK)      // 12
#define OFF_AH 0                 // 32 rows * 144B = 4608
#define OFF_AL 4608
#define OFF_BH 9216              // 64 rows * 144B = 9216
#define OFF_BL 18432
#define BUFSZ  27648
#define SMEM_TOTAL (2 * BUFSZ)   // 55296

__device__ __forceinline__ void cp16(uint32_t dst, const void* src) {
    asm volatile("cp.async.cg.shared.global [%0], [%1], 16;" :: "r"(dst), "l"(src));
}
__device__ __forceinline__ void ldm_x4(uint32_t r[4], uint32_t addr) {
    asm volatile("ldmatrix.sync.aligned.m8n8.x4.shared.b16 {%0,%1,%2,%3}, [%4];"
                 : "=r"(r[0]), "=r"(r[1]), "=r"(r[2]), "=r"(r[3]) : "r"(addr));
}
__device__ __forceinline__ void ldm_x4_t(uint32_t r[4], uint32_t addr) {
    asm volatile("ldmatrix.sync.aligned.m8n8.x4.trans.shared.b16 {%0,%1,%2,%3}, [%4];"
                 : "=r"(r[0]), "=r"(r[1]), "=r"(r[2]), "=r"(r[3]) : "r"(addr));
}
__device__ __forceinline__ void mma_bf16(float c[4], const uint32_t a[4],
                                         uint32_t b0, uint32_t b1) {
    asm volatile(
        "mma.sync.aligned.m16n8k16.row.col.f32.bf16.bf16.f32 "
        "{%0,%1,%2,%3}, {%4,%5,%6,%7}, {%8,%9}, {%0,%1,%2,%3};"
        : "+f"(c[0]), "+f"(c[1]), "+f"(c[2]), "+f"(c[3])
        : "r"(a[0]), "r"(a[1]), "r"(a[2]), "r"(a[3]), "r"(b0), "r"(b1));
}

__device__ __forceinline__ void issue_stage(uint32_t sbase, int buf, int s,
                                            int r0, int c0, int tid) {
    const int k0 = s * GBK;
    const uint32_t base = sbase + (uint32_t)buf * BUFSZ;
    // A: 32 rows x 8 chunks = 256 cp16 (x2 hi/lo) -> 1 per thread each
    {
        int m  = tid >> 3;               // 0..31
        int ch = tid & 7;
        uint32_t so = (uint32_t)(m * ROWB + ch * 16);
        const size_t aoff = (size_t)(r0 + m) * CDIM + k0 + ch * 8;
        cp16(base + OFF_AH + so, g_Ah + aoff);
        cp16(base + OFF_AL + so, g_Al + aoff);
    }
    // B: 64 k-rows x 8 chunks = 512 cp16 (x2 hi/lo) -> 2 per thread each
#pragma unroll
    for (int i = 0; i < 2; i++) {
        int c  = tid + i * 256;          // 0..511
        int kk = c >> 3;                 // 0..63
        int ch = c & 7;
        uint32_t so = (uint32_t)(kk * ROWB + ch * 16);
        const size_t boff = (size_t)(k0 + kk) * NPAD + c0 + ch * 8;
        cp16(base + OFF_BH + so, g_Wh + boff);
        cp16(base + OFF_BL + so, g_Wl + boff);
    }
}

__global__ void __launch_bounds__(256)
gemm_hmma_kernel(const float* __restrict__ bias, float* __restrict__ out) {
    extern __shared__ __align__(16) char smem[];
    const uint32_t sbase = smem_u32(smem);
    const int tid  = threadIdx.x;
    const int warp = tid >> 5;
    const int lane = tid & 31;
    const int wm   = warp & 1;           // 0..1 -> m offset wm*16
    const int wn   = warp >> 1;          // 0..3 -> n offset wn*16
    const int r0   = blockIdx.y * GBM;
    const int c0   = blockIdx.x * GBN;

    const int mat = lane >> 3, mr = lane & 7;
    const uint32_t aOff =
        (uint32_t)((wm * 16 + (mat & 1) * 8 + mr) * ROWB + (mat >> 1) * 16);
    const int bk  = lane & 15;
    const int bn8 = lane >> 4;
    const uint32_t bOff = (uint32_t)(bk * ROWB + (wn * 16 + bn8 * 8) * 2);

    float acc[2][4];
#pragma unroll
    for (int i = 0; i < 2; i++)
#pragma unroll
        for (int j = 0; j < 4; j++) acc[i][j] = 0.f;

    issue_stage(sbase, 0, 0, r0, c0, tid);
    asm volatile("cp.async.commit_group;" ::: "memory");

    for (int s = 0; s < NSTAGE; s++) {
        const int buf = s & 1;
        if (s + 1 < NSTAGE) {
            issue_stage(sbase, buf ^ 1, s + 1, r0, c0, tid);
            asm volatile("cp.async.commit_group;" ::: "memory");
            asm volatile("cp.async.wait_group 1;" ::: "memory");
        } else {
            asm volatile("cp.async.wait_group 0;" ::: "memory");
        }
        __syncthreads();

        const uint32_t bb = sbase + (uint32_t)buf * BUFSZ;
        const uint32_t aHb = bb + OFF_AH + aOff;
        const uint32_t aLb = bb + OFF_AL + aOff;
        const uint32_t bHb = bb + OFF_BH + bOff;
        const uint32_t bLb = bb + OFF_BL + bOff;

#pragma unroll
        for (int ks = 0; ks < 4; ks++) {
            const uint32_t kByte = (uint32_t)(ks * 16 * ROWB);
            uint32_t ah[4], al[4], bh[4], bl[4];
            ldm_x4(ah, aHb + ks * 32);
            ldm_x4(al, aLb + ks * 32);
            ldm_x4_t(bh, bHb + kByte);
            ldm_x4_t(bl, bLb + kByte);

            mma_bf16(acc[0], ah, bh[0], bh[1]);
            mma_bf16(acc[1], ah, bh[2], bh[3]);
            mma_bf16(acc[0], ah, bl[0], bl[1]);
            mma_bf16(acc[1], ah, bl[2], bl[3]);
            mma_bf16(acc[0], al, bh[0], bh[1]);
            mma_bf16(acc[1], al, bh[2], bh[3]);
        }
        __syncthreads();
    }

    // epilogue: c-frag: c0:(g,t2) c1:(g,t2+1) c2:(g+8,t2) c3:(g+8,t2+1)
    const int rA = r0 + wm * 16 + (lane >> 2);
    const int rB = rA + 8;
    const int cBase = c0 + wn * 16 + (lane & 3) * 2;
#pragma unroll
    for (int nb = 0; nb < 2; nb++) {
        int c = cBase + nb * 8;
        if (c < NCLS) {
            float bv = bias[c];
            out[(size_t)rA * NCLS + c] = acc[nb][0] + bv;
            out[(size_t)rB * NCLS + c] = acc[nb][2] + bv;
        }
        if (c + 1 < NCLS) {
            float bv = bias[c + 1];
            out[(size_t)rA * NCLS + c + 1] = acc[nb][1] + bv;
            out[(size_t)rB * NCLS + c + 1] = acc[nb][3] + bv;
        }
    }
}

// ============================================================================
extern "C" void kernel_launch(void* const* d_in, const int* in_sizes, int n_in,
                              void* d_out, int out_size) {
    const float* x1 = nullptr;
    const float* x2 = nullptr;
    const float* W  = nullptr;
    const float* bb = nullptr;
    for (int i = 0; i < n_in; i++) {
        if (in_sizes[i] == BATCH * NTOK * CDIM) {
            if (!x1) x1 = (const float*)d_in[i];
            else if (!x2) x2 = (const float*)d_in[i];
        } else if (in_sizes[i] == CDIM * NCLS) {
            W = (const float*)d_in[i];
        } else if (in_sizes[i] == NCLS) {
            bb = (const float*)d_in[i];
        }
    }
    float* out = (float*)d_out;

    dim3 g1(BATCH, 3);               // y=0,1: sgm; y=2: W split (overlapped)
    sgm_kernel<<<g1, 256>>>(x1, x2, W);

    static bool attr_done = false;
    if (!attr_done) {
        cudaFuncSetAttribute(gemm_hmma_kernel,
                             cudaFuncAttributeMaxDynamicSharedMemorySize, SMEM_TOTAL);
        attr_done = true;
    }
    dim3 g2(NPAD / GBN, (4 * BATCH) / GBM);   // 11 x 32 = 352
    gemm_hmma_kernel<<<g2, 256, SMEM_TOTAL>>>(bb, out);
}